// round 16
// baseline (speedup 1.0000x reference)
#include <cuda_runtime.h>

// MxCorrelation: out[b, (p+4)*9+(q+4), y, x] = (1/128) * sum_c a[b,c,y,x] * b[b,c,y+p,x+q]
// p,q in [-4,4], b zero-padded. in (8,128,128,128) f32, out (8,81,128,128) f32.
//
// R15: R2 champion skeleton (block-shared sB, cp.async double-buffer, LDG A,
// 3 p-groups, occ 3) + e2-via-shfl: the 3rd window LDS.128 per (c,pp) is pure
// cross-lane redundancy (e2(L) = e1(L+1)); replace with shfl_down(e1,1),
// lane31 -> zero (its e2 is the always-zero right pad). Crossbar volume -33%,
// fewer LDS wavefronts stealing issue/accept slots from the FFMA stream.

#define TY   4
#define CC   4
#define BR   (TY + 2)          // 6 b-rows per p-group
#define BW   144               // 4 halo | 128 interior | 12 pad (16B-aligned rows)
#define NTHR 128
#define NCH  (128 / CC)
#define SBHALF (CC * BR * BW * 4)

__global__ __launch_bounds__(NTHR, 3)
void corr_kernel(const float* __restrict__ A, const float* __restrict__ Bm,
                 float* __restrict__ O) {
    __shared__ __align__(16) float sB[2][CC][BR][BW];

    const int t    = threadIdx.x;
    const int lane = t & 31;
    const int yy   = t >> 5;
    const int x0   = lane << 2;

    const int y0 = blockIdx.x * TY;
    const int p0 = (int)blockIdx.y * 3 - 4;
    const int bb = blockIdx.z;

    const float* Ab = A  + (size_t)bb * 2097152;
    const float* Bb = Bm + (size_t)bb * 2097152;

    // zero both buffers once (halo + pad + invalid rows stay zero)
    float4* sB4 = (float4*)&sB[0][0][0][0];
#pragma unroll
    for (int i = 0; i < (2 * CC * BR * BW / 4 + NTHR - 1) / NTHR; i++) {
        int idx = t + i * NTHR;
        if (idx < 2 * CC * BR * BW / 4) sB4[idx] = make_float4(0.f, 0.f, 0.f, 0.f);
    }

    // hoisted fill descriptors: 6 interior float4 slots per thread
    const float* gptr[6];
    unsigned     sb0[6];
    bool         valid[6];
#pragma unroll
    for (int k = 0; k < 6; k++) {
        int idx = k * NTHR + t;
        int col = idx & 31;
        int row = idx >> 5;
        int c   = row / 6;
        int r   = row - c * 6;
        int gy  = y0 + p0 + r;
        valid[k] = (unsigned)gy < 128u;
        gptr[k]  = Bb + (size_t)c * 16384 + gy * 128 + col * 4;
        sb0[k]   = (unsigned)__cvta_generic_to_shared(&sB[0][c][r][4 + col * 4]);
    }
    __syncthreads();   // zeros visible before cp.async lands

    // prologue fill: chunk 0 -> buffer 0
#pragma unroll
    for (int k = 0; k < 6; k++) {
        if (valid[k])
            asm volatile("cp.async.cg.shared.global [%0], [%1], 16;\n"
                         :: "r"(sb0[k]), "l"(gptr[k]));
        gptr[k] += CC * 16384;
    }
    asm volatile("cp.async.commit_group;\n" ::: "memory");

    float acc[3][9][4];
#pragma unroll
    for (int pp = 0; pp < 3; pp++)
#pragma unroll
        for (int q = 0; q < 9; q++)
#pragma unroll
            for (int j = 0; j < 4; j++) acc[pp][q][j] = 0.0f;

    const float* Arow = Ab + (y0 + yy) * 128 + x0;

    for (int chunk = 0; chunk < NCH; chunk++) {
        const int buf  = chunk & 1;
        const int nbuf = buf ^ 1;

        // prefetch A (overlaps wait + barrier)
        float4 av[CC];
#pragma unroll
        for (int c = 0; c < CC; c++)
            av[c] = *(const float4*)(Arow + (size_t)(chunk * CC + c) * 16384);

        asm volatile("cp.async.wait_group 0;\n" ::: "memory");
        __syncthreads();

        if (chunk + 1 < NCH) {
#pragma unroll
            for (int k = 0; k < 6; k++) {
                if (valid[k])
                    asm volatile("cp.async.cg.shared.global [%0], [%1], 16;\n"
                                 :: "r"(sb0[k] + nbuf * (unsigned)SBHALF), "l"(gptr[k]));
                gptr[k] += CC * 16384;
            }
        }
        asm volatile("cp.async.commit_group;\n" ::: "memory");

        // compute: 4c x 3pp x (2 LDS.128 + 4 shfl + 36 FFMA)
#pragma unroll
        for (int c = 0; c < CC; c++) {
#pragma unroll
            for (int pp = 0; pp < 3; pp++) {
                const float* row = &sB[buf][c][yy + pp][0];
                float4 e0 = *(const float4*)&row[x0];
                float4 e1 = *(const float4*)&row[x0 + 4];
                float4 e2;
                e2.x = __shfl_down_sync(0xffffffffu, e1.x, 1);
                e2.y = __shfl_down_sync(0xffffffffu, e1.y, 1);
                e2.z = __shfl_down_sync(0xffffffffu, e1.z, 1);
                e2.w = __shfl_down_sync(0xffffffffu, e1.w, 1);
                if (lane == 31) { e2.x = 0.f; e2.y = 0.f; e2.z = 0.f; e2.w = 0.f; }
                float w[12];
                w[0] = e0.x; w[1] = e0.y; w[2]  = e0.z; w[3]  = e0.w;
                w[4] = e1.x; w[5] = e1.y; w[6]  = e1.z; w[7]  = e1.w;
                w[8] = e2.x; w[9] = e2.y; w[10] = e2.z; w[11] = e2.w;
#pragma unroll
                for (int q = 0; q < 9; q++) {
                    acc[pp][q][0] += av[c].x * w[q];
                    acc[pp][q][1] += av[c].y * w[q + 1];
                    acc[pp][q][2] += av[c].z * w[q + 2];
                    acc[pp][q][3] += av[c].w * w[q + 3];
                }
            }
        }
    }

    // epilogue: scale, float4 coalesced stores
    const float scale = 1.0f / 128.0f;
    float* Ob = O + (size_t)bb * 81 * 16384;
#pragma unroll
    for (int pp = 0; pp < 3; pp++) {
        int dbase = (p0 + pp + 4) * 9;
#pragma unroll
        for (int q = 0; q < 9; q++) {
            float4 v;
            v.x = acc[pp][q][0] * scale;
            v.y = acc[pp][q][1] * scale;
            v.z = acc[pp][q][2] * scale;
            v.w = acc[pp][q][3] * scale;
            *(float4*)&Ob[(size_t)(dbase + q) * 16384 + (y0 + yy) * 128 + x0] = v;
        }
    }
}

extern "C" void kernel_launch(void* const* d_in, const int* in_sizes, int n_in,
                              void* d_out, int out_size) {
    const float* A = (const float*)d_in[0];
    const float* B = (const float*)d_in[1];
    float*       O = (float*)d_out;

    dim3 grid(32, 3, 8);
    corr_kernel<<<grid, NTHR>>>(A, B, O);
}